// round 4
// baseline (speedup 1.0000x reference)
#include <cuda_runtime.h>
#include <cuda_bf16.h>
#include <cstdint>

// =====================================================================
// GraphConv on GB300 — family-generic PTX path (no tcgen05: harness
// compiles compute_103 PTX where tcgen05 is rejected by ptxas).
// Uses mma.sync m16n8k16 bf16 (HMMA) + ldmatrix + SW128 swizzle.
//   out = relu(F@W1 + A@(F@W2) + bias)
// P1: weight prep (W2^T bf16; W1^T hi/lo split)
// P2: Gt = W2^T @ F^T  (bf16, K=256)
// P3: out = relu([A|Fh|Fh|Fl] @ [Gt;Wh;Wl;Wh]^T + bias), K=2816
// =====================================================================

#define BATCH 16
#define NTOK  2048
#define DDIM  256
#define FDIM  256
#define KAUG  768
#define KC    64
#define NCH_BIG 44   // (2048+768)/64

// ---------------- device scratch (no allocs allowed) -----------------
__device__ __nv_bfloat16 g_Gt[(size_t)BATCH * FDIM * NTOK];  // [b][f][tok] 16MB
__device__ __nv_bfloat16 g_W2t[FDIM * DDIM];                 // [f][d]
__device__ __nv_bfloat16 g_Bw[FDIM * KAUG];                  // [f][Wh|Wl|Wh]

#define SMEM_SWIZZLE_128B(byte_offset) \
    ((byte_offset) ^ (((byte_offset) >> 3) & 0x70))

// SMEM: A0 | A1 | B0 | B1, each 128 rows x 128 bytes = 16KB
#define TILE_BYTES 16384
#define SM_A0 0
#define SM_B0 (2 * TILE_BYTES)
#define SMEM_BYTES (4 * TILE_BYTES)

__device__ __forceinline__ uint32_t smem_to_u32(const void* p) {
    uint32_t a;
    asm("{ .reg .u64 t; cvta.to.shared.u64 t, %1; cvt.u32.u64 %0, t; }"
        : "=r"(a) : "l"(p));
    return a;
}

__device__ __forceinline__ void ldsm_x4(uint32_t addr, uint32_t r[4]) {
    asm volatile("ldmatrix.sync.aligned.m8n8.x4.shared.b16 {%0,%1,%2,%3}, [%4];"
                 : "=r"(r[0]), "=r"(r[1]), "=r"(r[2]), "=r"(r[3]) : "r"(addr));
}

__device__ __forceinline__ void mma_16816(float c[4], const uint32_t a[4],
                                          uint32_t b0, uint32_t b1) {
    asm volatile(
        "mma.sync.aligned.m16n8k16.row.col.f32.bf16.bf16.f32 "
        "{%0,%1,%2,%3}, {%4,%5,%6,%7}, {%8,%9}, {%0,%1,%2,%3};"
        : "+f"(c[0]), "+f"(c[1]), "+f"(c[2]), "+f"(c[3])
        : "r"(a[0]), "r"(a[1]), "r"(a[2]), "r"(a[3]), "r"(b0), "r"(b1));
}

__device__ __forceinline__ void store_bf4(char* tile, uint32_t byte_off,
                                          float a, float b, float c, float d)
{
    __nv_bfloat162 p0, p1;
    p0.x = __float2bfloat16(a); p0.y = __float2bfloat16(b);
    p1.x = __float2bfloat16(c); p1.y = __float2bfloat16(d);
    uint2 v;
    v.x = *reinterpret_cast<uint32_t*>(&p0);
    v.y = *reinterpret_cast<uint32_t*>(&p1);
    *reinterpret_cast<uint2*>(tile + SMEM_SWIZZLE_128B(byte_off)) = v;
}

__device__ __forceinline__ float lo_part(float v) {
    return v - __bfloat162float(__float2bfloat16(v));
}

// ---- producers: tile = 128 rows x 64 bf16 (128B/row), SW128 swizzled ----
// fp32 source -> bf16
__device__ __forceinline__ void produce_f32(char* tile, const float* src,
                                            int stride_f, int tid) {
#pragma unroll
    for (int it = 0; it < 8; it++) {
        int lin = it * 256 + tid;          // 2048 float4 vecs
        int r = lin >> 4, c4 = lin & 15;
        float4 v = *reinterpret_cast<const float4*>(src + (size_t)r * stride_f + c4 * 4);
        store_bf4(tile, (uint32_t)(r * 128 + c4 * 8), v.x, v.y, v.z, v.w);
    }
}
// fp32 source -> lo residual bf16
__device__ __forceinline__ void produce_f32_lo(char* tile, const float* src,
                                               int stride_f, int tid) {
#pragma unroll
    for (int it = 0; it < 8; it++) {
        int lin = it * 256 + tid;
        int r = lin >> 4, c4 = lin & 15;
        float4 v = *reinterpret_cast<const float4*>(src + (size_t)r * stride_f + c4 * 4);
        store_bf4(tile, (uint32_t)(r * 128 + c4 * 8),
                  lo_part(v.x), lo_part(v.y), lo_part(v.z), lo_part(v.w));
    }
}
// bf16 source direct copy
__device__ __forceinline__ void produce_bf16(char* tile, const __nv_bfloat16* src,
                                             int stride_e, int tid) {
#pragma unroll
    for (int it = 0; it < 4; it++) {
        int lin = it * 256 + tid;          // 1024 uint4 vecs
        int r = lin >> 3, cv = lin & 7;
        uint4 v = *reinterpret_cast<const uint4*>(src + (size_t)r * stride_e + cv * 8);
        *reinterpret_cast<uint4*>(tile + SMEM_SWIZZLE_128B((uint32_t)(r * 128 + cv * 16))) = v;
    }
}

// ---- consumer: one K=64 chunk of 128x128 tile via mma.sync ----
// warp (wm in 0..3: 32 M-rows; wn in 0..1: 64 N-cols), acc[2][8][4]
__device__ __forceinline__ void consume_chunk(uint32_t aBase, uint32_t bBase,
                                              int wm, int wn, int lane,
                                              float acc[2][8][4]) {
    // ldmatrix lane-address components
    int arow = wm * 32 + (lane & 15);
    int akb  = ((lane >> 4) & 1) * 16;
    int bn   = (lane & 7) + ((lane >> 4) << 3);   // n within 16-row pair
    int bkb  = ((lane >> 3) & 1) * 16;
#pragma unroll
    for (int ks = 0; ks < 4; ks++) {
        uint32_t a[2][4];
#pragma unroll
        for (int mt = 0; mt < 2; mt++) {
            uint32_t off = (uint32_t)((arow + mt * 16) * 128 + ks * 32 + akb);
            ldsm_x4(aBase + SMEM_SWIZZLE_128B(off), a[mt]);
        }
#pragma unroll
        for (int ntp = 0; ntp < 4; ntp++) {
            uint32_t off = (uint32_t)((wn * 64 + ntp * 16 + bn) * 128 + ks * 32 + bkb);
            uint32_t bq[4];
            ldsm_x4(bBase + SMEM_SWIZZLE_128B(off), bq);
#pragma unroll
            for (int mt = 0; mt < 2; mt++) {
                mma_16816(acc[mt][2 * ntp],     a[mt], bq[0], bq[1]);
                mma_16816(acc[mt][2 * ntp + 1], a[mt], bq[2], bq[3]);
            }
        }
    }
}

// =====================================================================
// P1: weight prep
// =====================================================================
__global__ void prep_weights_kernel(const float* __restrict__ w)
{
    int i = blockIdx.x * blockDim.x + threadIdx.x;   // over FDIM*DDIM = 65536
    if (i >= FDIM * DDIM) return;
    int n = i / DDIM, d = i % DDIM;
    float w1 = w[d * FDIM + n];             // W1[d][n]
    float w2 = w[(DDIM + d) * FDIM + n];    // W2[d][n]
    __nv_bfloat16 h = __float2bfloat16(w1);
    __nv_bfloat16 l = __float2bfloat16(w1 - __bfloat162float(h));
    g_Bw[n * KAUG + d]       = h;   // pairs with F_hi
    g_Bw[n * KAUG + 256 + d] = l;   // pairs with F_hi
    g_Bw[n * KAUG + 512 + d] = h;   // pairs with F_lo
    g_W2t[n * DDIM + d] = __float2bfloat16(w2);
}

// =====================================================================
// P2: Gt[b][f][tok] = (F@W2)^T  computed as W2^T @ F^T
//   CTA tile: M=128 (f), N=128 (tok), K=256 (4 chunks)
// grid: (ntile=16, mtile=2, b=16), block 256
// =====================================================================
__global__ void __launch_bounds__(256, 2)
gemm_gt_kernel(const float* __restrict__ F)
{
    extern __shared__ char smem[];
    uint32_t smem_u = smem_to_u32(smem);
    int tid = threadIdx.x;
    int wid = tid >> 5, lane = tid & 31;
    int wm = wid & 3, wn = wid >> 2;
    int ntile = blockIdx.x, mtile = blockIdx.y, b = blockIdx.z;
    int mbase = mtile * 128, nbase = ntile * 128;

    float acc[2][8][4];
#pragma unroll
    for (int i = 0; i < 2; i++)
#pragma unroll
        for (int j = 0; j < 8; j++)
#pragma unroll
            for (int q = 0; q < 4; q++) acc[i][j][q] = 0.f;

    for (int ch = 0; ch < 4; ch++) {
        int p = ch & 1;
        int kbase = ch * KC;
        char* at = smem + SM_A0 + p * TILE_BYTES;
        char* bt = smem + SM_B0 + p * TILE_BYTES;
        // A: W2t rows [mbase,+128), bf16
        produce_bf16(at, g_W2t + (size_t)mbase * DDIM + kbase, DDIM, tid);
        // B: F rows [nbase,+128) of batch b, fp32->bf16
        produce_f32(bt, F + ((size_t)b * NTOK + nbase) * DDIM + kbase, DDIM, tid);
        __syncthreads();
        consume_chunk(smem_u + SM_A0 + p * TILE_BYTES,
                      smem_u + SM_B0 + p * TILE_BYTES, wm, wn, lane, acc);
        __syncthreads();
    }

    // epilogue: store bf16 Gt
    int tg = lane >> 2, tc = (lane & 3) * 2;
#pragma unroll
    for (int mt = 0; mt < 2; mt++) {
        int f = mbase + wm * 32 + mt * 16 + tg;
        __nv_bfloat16* g0 = g_Gt + ((size_t)b * FDIM + f) * NTOK;
        __nv_bfloat16* g1 = g0 + (size_t)8 * NTOK;
#pragma unroll
        for (int nt = 0; nt < 8; nt++) {
            int col = nbase + wn * 64 + nt * 8 + tc;
            __nv_bfloat162 v0, v1;
            v0.x = __float2bfloat16(acc[mt][nt][0]);
            v0.y = __float2bfloat16(acc[mt][nt][1]);
            v1.x = __float2bfloat16(acc[mt][nt][2]);
            v1.y = __float2bfloat16(acc[mt][nt][3]);
            *reinterpret_cast<__nv_bfloat162*>(g0 + col) = v0;
            *reinterpret_cast<__nv_bfloat162*>(g1 + col) = v1;
        }
    }
}

// =====================================================================
// P3: out[b][tok][f] = relu([A|Fh|Fh|Fl] @ Baug^T + bias)
//   CTA tile: M=128 (tok), N=128 (f), K=2816 (44 chunks)
// grid: (ntile=2, mtile=16, b=16), block 256
// =====================================================================
__global__ void __launch_bounds__(256, 2)
gemm_big_kernel(const float* __restrict__ A, const float* __restrict__ F,
                const float* __restrict__ bias, float* __restrict__ out)
{
    extern __shared__ char smem[];
    uint32_t smem_u = smem_to_u32(smem);
    int tid = threadIdx.x;
    int wid = tid >> 5, lane = tid & 31;
    int wm = wid & 3, wn = wid >> 2;
    int ntile = blockIdx.x, mtile = blockIdx.y, b = blockIdx.z;
    int mbase = mtile * 128, nbase = ntile * 128;

    float acc[2][8][4];
#pragma unroll
    for (int i = 0; i < 2; i++)
#pragma unroll
        for (int j = 0; j < 8; j++)
#pragma unroll
            for (int q = 0; q < 4; q++) acc[i][j][q] = 0.f;

    for (int ch = 0; ch < NCH_BIG; ch++) {
        int p = ch & 1;
        int kbase = ch * KC;
        char* at = smem + SM_A0 + p * TILE_BYTES;
        char* bt = smem + SM_B0 + p * TILE_BYTES;

        // ---- A-side [128 x 64] ----
        if (kbase < 2048) {
            produce_f32(at, A + ((size_t)b * NTOK + mbase) * NTOK + kbase, NTOK, tid);
        } else {
            int kk = kbase - 2048;
            int blk = kk >> 8;              // 0,1: F_hi   2: F_lo
            int dbase = kk & 255;
            const float* src = F + ((size_t)b * NTOK + mbase) * DDIM + dbase;
            if (blk == 2) produce_f32_lo(at, src, DDIM, tid);
            else          produce_f32(at, src, DDIM, tid);
        }
        // ---- B-side [128 x 64] ----
        if (kbase < 2048) {
            produce_bf16(bt, g_Gt + ((size_t)b * FDIM + nbase) * NTOK + kbase, NTOK, tid);
        } else {
            int koff = kbase - 2048;
            produce_bf16(bt, g_Bw + (size_t)nbase * KAUG + koff, KAUG, tid);
        }
        __syncthreads();
        consume_chunk(smem_u + SM_A0 + p * TILE_BYTES,
                      smem_u + SM_B0 + p * TILE_BYTES, wm, wn, lane, acc);
        __syncthreads();
    }

    // epilogue: +bias, relu, fp32 stores
    int tg = lane >> 2, tc = (lane & 3) * 2;
#pragma unroll
    for (int mt = 0; mt < 2; mt++) {
        int r0 = mbase + wm * 32 + mt * 16 + tg;
        float* row0 = out + ((size_t)b * NTOK + r0) * FDIM;
        float* row1 = row0 + (size_t)8 * FDIM;
#pragma unroll
        for (int nt = 0; nt < 8; nt++) {
            int col = nbase + wn * 64 + nt * 8 + tc;
            float bb0 = __ldg(bias + col), bb1 = __ldg(bias + col + 1);
            float2 v0, v1;
            v0.x = fmaxf(acc[mt][nt][0] + bb0, 0.f);
            v0.y = fmaxf(acc[mt][nt][1] + bb1, 0.f);
            v1.x = fmaxf(acc[mt][nt][2] + bb0, 0.f);
            v1.y = fmaxf(acc[mt][nt][3] + bb1, 0.f);
            *reinterpret_cast<float2*>(row0 + col) = v0;
            *reinterpret_cast<float2*>(row1 + col) = v1;
        }
    }
}

// =====================================================================
// Launch
// =====================================================================
extern "C" void kernel_launch(void* const* d_in, const int* in_sizes, int n_in,
                              void* d_out, int out_size)
{
    const float* F    = (const float*)d_in[0];   // [16,2048,256]
    const float* A    = (const float*)d_in[1];   // [16,2048,2048]
    const float* W    = (const float*)d_in[2];   // [512,256]
    const float* bias = (const float*)d_in[3];   // [256]
    float* out = (float*)d_out;                  // [16,2048,256]

    cudaFuncSetAttribute(gemm_gt_kernel,
                         cudaFuncAttributeMaxDynamicSharedMemorySize, SMEM_BYTES);
    cudaFuncSetAttribute(gemm_big_kernel,
                         cudaFuncAttributeMaxDynamicSharedMemorySize, SMEM_BYTES);

    prep_weights_kernel<<<256, 256>>>(W);
    gemm_gt_kernel<<<dim3(16, 2, 16), 256, SMEM_BYTES>>>(F);
    gemm_big_kernel<<<dim3(2, 16, 16), 256, SMEM_BYTES>>>(A, F, bias, out);
}